// round 1
// baseline (speedup 1.0000x reference)
#include <cuda_runtime.h>
#include <math.h>

#define BB 32
#define TT 200
#define EE 32
#define HH 128
#define VV 8000
#define MM (BB*TT)   // 6400

// Scratch (device globals; no allocation allowed)
__device__ float g_ux[MM*HH];     // [m][h], m = b*T + t
__device__ float g_hsT[HH*MM];    // [h][m]  (transposed for GEMM A-tile loads)
__device__ float g_VwT[HH*VV];    // [h][v]  (transposed for GEMM B-tile loads)

// ---------------------------------------------------------------------------
// Transpose Vw [V,H] -> VwT [H,V]
// ---------------------------------------------------------------------------
__global__ void k_transpose(const float* __restrict__ Vw) {
    __shared__ float tile[32][33];
    int v0 = blockIdx.x * 32, h0 = blockIdx.y * 32;
    int tx = threadIdx.x, ty = threadIdx.y;           // 32 x 8
    #pragma unroll
    for (int i = ty; i < 32; i += 8)
        tile[i][tx] = Vw[(size_t)(v0 + i) * HH + h0 + tx];
    __syncthreads();
    #pragma unroll
    for (int i = ty; i < 32; i += 8)
        g_VwT[(size_t)(h0 + i) * VV + v0 + tx] = tile[tx][i];
}

// ---------------------------------------------------------------------------
// ux[m][h] = sum_e x[m][e] * Uw[h][e] + Ub[h] + Wb[h]     (m = b*T + t)
// 200 blocks x 256 threads; each block handles 32 rows of x.
// ---------------------------------------------------------------------------
__global__ void k_ux(const float* __restrict__ x, const float* __restrict__ Uw,
                     const float* __restrict__ Ub, const float* __restrict__ Wb) {
    __shared__ float UwT[EE][HH];   // 16 KB, UwT[e][h] = Uw[h][e]
    __shared__ float xs[32][EE];    // 4 KB
    __shared__ float bias[HH];
    int tid = threadIdx.x;

    // Load Uw [H,E] coalesced, store transposed
    for (int f = tid; f < HH * EE / 4; f += 256) {
        int h = f / (EE / 4), c = f % (EE / 4);
        float4 u = ((const float4*)Uw)[f];
        UwT[c * 4 + 0][h] = u.x;
        UwT[c * 4 + 1][h] = u.y;
        UwT[c * 4 + 2][h] = u.z;
        UwT[c * 4 + 3][h] = u.w;
    }
    if (tid < HH) bias[tid] = Ub[tid] + Wb[tid];

    int m0 = blockIdx.x * 32;
    // Load 32 rows of x (each E=32 floats = 8 float4): exactly 256 float4
    {
        int r = tid / 8, c = tid % 8;
        ((float4*)&xs[r][0])[c] = ((const float4*)x)[(size_t)(m0 + r) * (EE / 4) + c];
    }
    __syncthreads();

    int h = tid % HH;
    int half = tid / HH;   // 0 or 1
    #pragma unroll
    for (int rr = 0; rr < 16; rr++) {
        int r = half * 16 + rr;
        float acc = bias[h];
        const float4* xv = (const float4*)&xs[r][0];
        #pragma unroll
        for (int e4 = 0; e4 < EE / 4; e4++) {
            float4 xf = xv[e4];
            acc += UwT[e4 * 4 + 0][h] * xf.x;
            acc += UwT[e4 * 4 + 1][h] * xf.y;
            acc += UwT[e4 * 4 + 2][h] * xf.z;
            acc += UwT[e4 * 4 + 3][h] * xf.w;
        }
        g_ux[(size_t)(m0 + r) * HH + h] = acc;
    }
}

// ---------------------------------------------------------------------------
// Recurrence: per-batch block. h_t = tanh(Ww h_{t-1} + ux_t)
// Writes hs transposed to g_hsT[h][b*T+t]; final h to out_hidden[b][h].
// ---------------------------------------------------------------------------
__global__ void k_rnn(const float* __restrict__ Ww, float* __restrict__ out_hidden) {
    extern __shared__ float sm[];
    float* WwT = sm;            // [k][j] = Ww[j][k], 64 KB
    float* hbuf = sm + HH * HH; // 128 floats

    int j = threadIdx.x;   // 0..127
    int b = blockIdx.x;

    // Load WwT (uncoalesced global read, conflict-free SMEM store; one-time)
    #pragma unroll 4
    for (int k = 0; k < HH; k++)
        WwT[k * HH + j] = Ww[j * HH + k];
    hbuf[j] = 0.0f;
    __syncthreads();

    const float* uxb = g_ux + (size_t)b * TT * HH;
    float v = 0.0f;
    for (int t = 0; t < TT; t++) {
        float a0 = 0.f, a1 = 0.f, a2 = 0.f, a3 = 0.f;
        const float4* h4 = (const float4*)hbuf;
        #pragma unroll
        for (int kk = 0; kk < HH / 4; kk++) {
            float4 hv = h4[kk];
            a0 += WwT[(4 * kk + 0) * HH + j] * hv.x;
            a1 += WwT[(4 * kk + 1) * HH + j] * hv.y;
            a2 += WwT[(4 * kk + 2) * HH + j] * hv.z;
            a3 += WwT[(4 * kk + 3) * HH + j] * hv.w;
        }
        v = tanhf((a0 + a1) + (a2 + a3) + uxb[t * HH + j]);
        __syncthreads();
        hbuf[j] = v;
        __syncthreads();
        g_hsT[(size_t)j * MM + b * TT + t] = v;
    }
    out_hidden[b * HH + j] = v;
}

// ---------------------------------------------------------------------------
// Output GEMM: out[m][v] = sum_h hsT[h][m] * VwT[h][v] + Vb[v]
// 64x64 tile, K=128 fully resident in SMEM, 256 threads, 4x4 microtile.
// ---------------------------------------------------------------------------
#define BM 64
#define BN 64
__global__ void k_gemm(const float* __restrict__ Vb, float* __restrict__ out) {
    extern __shared__ float sm[];
    float* As = sm;              // [k][m], 128*64 floats, 32 KB
    float* Bs = sm + HH * BM;    // [k][n], 32 KB

    int tid = threadIdx.x;
    int m0 = blockIdx.y * BM, n0 = blockIdx.x * BN;

    // Load A tile: coalesced (hsT rows contiguous in m), conflict-free STS
    #pragma unroll
    for (int i = 0; i < 8; i++) {
        int f = tid + i * 256;                 // 2048 float4 total
        int k = f / (BM / 4), c = f % (BM / 4);
        ((float4*)As)[f] = ((const float4*)(g_hsT + (size_t)k * MM + m0))[c];
    }
    // Load B tile
    #pragma unroll
    for (int i = 0; i < 8; i++) {
        int f = tid + i * 256;
        int k = f / (BN / 4), c = f % (BN / 4);
        ((float4*)Bs)[f] = ((const float4*)(g_VwT + (size_t)k * VV + n0))[c];
    }
    __syncthreads();

    int ty = tid / 16, tx = tid % 16;
    float acc[4][4] = {};

    #pragma unroll 8
    for (int k = 0; k < HH; k++) {
        float4 a = *(const float4*)(As + k * BM + ty * 4);
        float4 bq = *(const float4*)(Bs + k * BN + tx * 4);
        float av[4] = {a.x, a.y, a.z, a.w};
        float bv[4] = {bq.x, bq.y, bq.z, bq.w};
        #pragma unroll
        for (int i = 0; i < 4; i++)
            #pragma unroll
            for (int jj = 0; jj < 4; jj++)
                acc[i][jj] += av[i] * bv[jj];
    }

    float4 vb = *(const float4*)(Vb + n0 + tx * 4);
    #pragma unroll
    for (int i = 0; i < 4; i++) {
        float4 o;
        o.x = acc[i][0] + vb.x;
        o.y = acc[i][1] + vb.y;
        o.z = acc[i][2] + vb.z;
        o.w = acc[i][3] + vb.w;
        *(float4*)(out + (size_t)(m0 + ty * 4 + i) * VV + n0 + tx * 4) = o;
    }
}

// ---------------------------------------------------------------------------
extern "C" void kernel_launch(void* const* d_in, const int* in_sizes, int n_in,
                              void* d_out, int out_size) {
    const float* x  = (const float*)d_in[0];
    const float* Ww = (const float*)d_in[1];
    const float* Wb = (const float*)d_in[2];
    const float* Uw = (const float*)d_in[3];
    const float* Ub = (const float*)d_in[4];
    const float* Vw = (const float*)d_in[5];
    const float* Vb = (const float*)d_in[6];
    float* out = (float*)d_out;

    cudaFuncSetAttribute(k_rnn,  cudaFuncAttributeMaxDynamicSharedMemorySize,
                         (HH * HH + HH) * 4);
    cudaFuncSetAttribute(k_gemm, cudaFuncAttributeMaxDynamicSharedMemorySize,
                         2 * HH * BM * 4);

    k_transpose<<<dim3(VV / 32, HH / 32), dim3(32, 8)>>>(Vw);
    k_ux<<<MM / 32, 256>>>(x, Uw, Ub, Wb);
    k_rnn<<<BB, HH, (HH * HH + HH) * 4>>>(Ww, out + (size_t)MM * VV);
    k_gemm<<<dim3(VV / BN, MM / BM), 256, 2 * HH * BM * 4>>>(Vb, out);
}

// round 2
// speedup vs baseline: 1.5271x; 1.5271x over previous
#include <cuda_runtime.h>
#include <math.h>
#include <stdint.h>

#define BB 32
#define TT 200
#define EE 32
#define HH 128
#define VV 8000
#define MM (BB*TT)   // 6400

// Scratch (device globals; no allocation allowed)
__device__ float g_ux[MM*HH];     // [m][h], m = b*T + t
__device__ float g_hs[MM*HH];     // [m][h] row-major (GEMM A operand)

// ---------------------------------------------------------------------------
// helpers
// ---------------------------------------------------------------------------
__device__ __forceinline__ float to_tf32(float x) {
    unsigned u;
    asm("cvt.rna.tf32.f32 %0, %1;" : "=r"(u) : "f"(x));
    return __uint_as_float(u);
}

__device__ __forceinline__ void mma8(float c[4], const float4& a, float bx, float by) {
    asm("mma.sync.aligned.m16n8k8.row.col.f32.tf32.tf32.f32 "
        "{%0,%1,%2,%3},{%4,%5,%6,%7},{%8,%9},{%0,%1,%2,%3};"
        : "+f"(c[0]), "+f"(c[1]), "+f"(c[2]), "+f"(c[3])
        : "r"(__float_as_uint(a.x)), "r"(__float_as_uint(a.y)),
          "r"(__float_as_uint(a.z)), "r"(__float_as_uint(a.w)),
          "r"(__float_as_uint(bx)), "r"(__float_as_uint(by)));
}

// ---------------------------------------------------------------------------
// ux[m][h] = sum_e x[m][e] * Uw[h][e] + Ub[h] + Wb[h]
// ---------------------------------------------------------------------------
__global__ void k_ux(const float* __restrict__ x, const float* __restrict__ Uw,
                     const float* __restrict__ Ub, const float* __restrict__ Wb) {
    __shared__ float UwT[EE][HH];
    __shared__ float xs[32][EE];
    __shared__ float bias[HH];
    int tid = threadIdx.x;

    for (int f = tid; f < HH * EE / 4; f += 256) {
        int h = f / (EE / 4), c = f % (EE / 4);
        float4 u = ((const float4*)Uw)[f];
        UwT[c * 4 + 0][h] = u.x;
        UwT[c * 4 + 1][h] = u.y;
        UwT[c * 4 + 2][h] = u.z;
        UwT[c * 4 + 3][h] = u.w;
    }
    if (tid < HH) bias[tid] = Ub[tid] + Wb[tid];

    int m0 = blockIdx.x * 32;
    {
        int r = tid / 8, c = tid % 8;
        ((float4*)&xs[r][0])[c] = ((const float4*)x)[(size_t)(m0 + r) * (EE / 4) + c];
    }
    __syncthreads();

    int h = tid % HH;
    int half = tid / HH;
    #pragma unroll
    for (int rr = 0; rr < 16; rr++) {
        int r = half * 16 + rr;
        float acc = bias[h];
        const float4* xv = (const float4*)&xs[r][0];
        #pragma unroll
        for (int e4 = 0; e4 < EE / 4; e4++) {
            float4 xf = xv[e4];
            acc += UwT[e4 * 4 + 0][h] * xf.x;
            acc += UwT[e4 * 4 + 1][h] * xf.y;
            acc += UwT[e4 * 4 + 2][h] * xf.z;
            acc += UwT[e4 * 4 + 3][h] * xf.w;
        }
        g_ux[(size_t)(m0 + r) * HH + h] = acc;
    }
}

// ---------------------------------------------------------------------------
// Recurrence: per-batch block, double-buffered h (1 sync/step).
// Writes hs row-major to g_hs[m][h]; final h to out_hidden.
// ---------------------------------------------------------------------------
__global__ void k_rnn(const float* __restrict__ Ww, float* __restrict__ out_hidden) {
    extern __shared__ float sm[];
    float* WwT = sm;              // [k][j] = Ww[j][k]
    float* hb  = sm + HH * HH;    // two buffers of HH

    int j = threadIdx.x;
    int b = blockIdx.x;

    #pragma unroll 4
    for (int k = 0; k < HH; k++)
        WwT[k * HH + j] = Ww[j * HH + k];
    hb[j] = 0.0f;
    __syncthreads();

    const float* uxb = g_ux + (size_t)b * TT * HH;
    float* hs_out = g_hs + (size_t)b * TT * HH;
    float v = 0.0f;
    int p = 0;
    for (int t = 0; t < TT; t++) {
        const float* hcur = hb + p * HH;
        float a0 = 0.f, a1 = 0.f, a2 = 0.f, a3 = 0.f;
        const float4* h4 = (const float4*)hcur;
        #pragma unroll
        for (int kk = 0; kk < HH / 4; kk++) {
            float4 hv = h4[kk];
            a0 += WwT[(4 * kk + 0) * HH + j] * hv.x;
            a1 += WwT[(4 * kk + 1) * HH + j] * hv.y;
            a2 += WwT[(4 * kk + 2) * HH + j] * hv.z;
            a3 += WwT[(4 * kk + 3) * HH + j] * hv.w;
        }
        v = tanhf((a0 + a1) + (a2 + a3) + uxb[t * HH + j]);
        hb[(1 - p) * HH + j] = v;
        hs_out[t * HH + j] = v;
        __syncthreads();
        p = 1 - p;
    }
    out_hidden[b * HH + j] = v;
}

// ---------------------------------------------------------------------------
// Output GEMM via mma.sync tf32: out[m][v] = sum_h hs[m][h]*Vw[v][h] + Vb[v]
// BM=64, BN=128, K=128 fully resident; fragment-shuffled SMEM (LDS.128 frags).
// 256 threads = 8 warps (2 M x 4 N), each warp 32x32 (2x4 m16n8k8 tiles).
// ---------------------------------------------------------------------------
#define BM 64
#define BN 128

__global__ void __launch_bounds__(256, 2)
k_gemm(const float* __restrict__ Vw, const float* __restrict__ Vb,
       float* __restrict__ out) {
    extern __shared__ float sm[];
    float* As = sm;                 // 16 kg * 4 im * 128 = 8192 floats (32KB)
    float* Bs = sm + 16 * 4 * 128;  // 16 kg * 8 ip * 128 = 16384 floats (64KB)

    int tid  = threadIdx.x;
    int warp = tid >> 5;
    int lane = tid & 31;
    int m0 = blockIdx.y * BM;
    int n0 = blockIdx.x * BN;

    int s  = lane >> 3;        // 0..3
    int kl = lane & 7;         // 0..7

    // ---- Load A tile (hs[m0..m0+64][0..128]) into shuffled layout ----
    // patch it: im = it>>6 (0..3), q = (it>>4)&3, kg = it&15
    #pragma unroll
    for (int i = 0; i < 32; i++) {
        int it = warp + i * 8;                 // 0..255
        int im = it >> 6, q = (it >> 4) & 3, kg = it & 15;
        int r = 2 * q + (s & 1) + 8 * (s >> 1);
        int k = kg * 8 + kl;
        float v = g_hs[(size_t)(m0 + im * 16 + r) * HH + k];
        int ldst = ((r & 7) << 2) | (k & 3);
        int reg  = (r >> 3) + 2 * ((k & 7) >> 2);
        As[(kg * 4 + im) * 128 + ldst * 4 + reg] = to_tf32(v);
    }
    // ---- Load B tile (Vw[n0..n0+128][0..128]) into shuffled layout ----
    #pragma unroll
    for (int i = 0; i < 64; i++) {
        int it = warp + i * 8;                 // 0..511
        int ip = it >> 6, q = (it >> 4) & 3, kg = it & 15;
        int nn = 16 * ip + 2 * q + (s & 1) + 8 * (s >> 1);
        int k = kg * 8 + kl;
        int gn = n0 + nn;
        float v = (gn < VV) ? Vw[(size_t)gn * HH + k] : 0.0f;
        int ldst = ((nn & 7) << 2) | (k & 3);
        int reg  = ((nn >> 3) & 1) * 2 + ((k & 7) >> 2);
        Bs[(kg * 8 + ip) * 128 + ldst * 4 + reg] = to_tf32(v);
    }
    __syncthreads();

    int wm = warp >> 2;   // 0..1
    int wn = warp & 3;    // 0..3

    float c[2][4][4];
    #pragma unroll
    for (int a = 0; a < 2; a++)
        #pragma unroll
        for (int b = 0; b < 4; b++)
            #pragma unroll
            for (int d = 0; d < 4; d++) c[a][b][d] = 0.0f;

    const float4* As4 = (const float4*)As;
    const float4* Bs4 = (const float4*)Bs;

    #pragma unroll
    for (int kg = 0; kg < 16; kg++) {
        float4 a0 = As4[(kg * 4 + wm * 2 + 0) * 32 + lane];
        float4 a1 = As4[(kg * 4 + wm * 2 + 1) * 32 + lane];
        float4 b0 = Bs4[(kg * 8 + wn * 2 + 0) * 32 + lane];
        float4 b1 = Bs4[(kg * 8 + wn * 2 + 1) * 32 + lane];
        mma8(c[0][0], a0, b0.x, b0.y);
        mma8(c[0][1], a0, b0.z, b0.w);
        mma8(c[0][2], a0, b1.x, b1.y);
        mma8(c[0][3], a0, b1.z, b1.w);
        mma8(c[1][0], a1, b0.x, b0.y);
        mma8(c[1][1], a1, b0.z, b0.w);
        mma8(c[1][2], a1, b1.x, b1.y);
        mma8(c[1][3], a1, b1.z, b1.w);
    }

    // ---- Epilogue ----
    #pragma unroll
    for (int im = 0; im < 2; im++) {
        int row = m0 + wm * 32 + im * 16 + (lane >> 2);
        #pragma unroll
        for (int nt = 0; nt < 4; nt++) {
            int col = n0 + wn * 32 + nt * 8 + (lane & 3) * 2;
            if (col < VV) {
                float vbx = Vb[col], vby = Vb[col + 1];
                float2 o0 = make_float2(c[im][nt][0] + vbx, c[im][nt][1] + vby);
                float2 o1 = make_float2(c[im][nt][2] + vbx, c[im][nt][3] + vby);
                *(float2*)(out + (size_t)row * VV + col) = o0;
                *(float2*)(out + (size_t)(row + 8) * VV + col) = o1;
            }
        }
    }
}

// ---------------------------------------------------------------------------
extern "C" void kernel_launch(void* const* d_in, const int* in_sizes, int n_in,
                              void* d_out, int out_size) {
    const float* x  = (const float*)d_in[0];
    const float* Ww = (const float*)d_in[1];
    const float* Wb = (const float*)d_in[2];
    const float* Uw = (const float*)d_in[3];
    const float* Ub = (const float*)d_in[4];
    const float* Vw = (const float*)d_in[5];
    const float* Vb = (const float*)d_in[6];
    float* out = (float*)d_out;

    cudaFuncSetAttribute(k_rnn,  cudaFuncAttributeMaxDynamicSharedMemorySize,
                         (HH * HH + 2 * HH) * 4);
    cudaFuncSetAttribute(k_gemm, cudaFuncAttributeMaxDynamicSharedMemorySize,
                         (16 * 4 * 128 + 16 * 8 * 128) * 4);

    k_ux<<<MM / 32, 256>>>(x, Uw, Ub, Wb);
    k_rnn<<<BB, HH, (HH * HH + 2 * HH) * 4>>>(Ww, out + (size_t)MM * VV);
    k_gemm<<<dim3((VV + BN - 1) / BN, MM / BM), 256,
             (16 * 4 * 128 + 16 * 8 * 128) * 4>>>(Vw, Vb, out);
}

// round 3
// speedup vs baseline: 2.2910x; 1.5002x over previous
#include <cuda_runtime.h>
#include <math.h>
#include <stdint.h>

#define BB 32
#define TT 200
#define EE 32
#define HH 128
#define VV 8000
#define MM (BB*TT)            // 6400
#define NT ((VV + 127) / 128) // 63 n-tiles
#define MT (MM / 64)          // 100 m-tiles

// Scratch (device globals; no allocation allowed)
__device__ float g_ux[MM*HH];            // [m][h]
__device__ float g_Afrag[MT*16*4*128];   // A fragments, tf32 (3.3 MB)
__device__ float g_Bfrag[NT*16*8*128];   // B fragments, tf32 (4.1 MB)

// ---------------------------------------------------------------------------
__device__ __forceinline__ float to_tf32(float x) {
    unsigned u;
    asm("cvt.rna.tf32.f32 %0, %1;" : "=r"(u) : "f"(x));
    return __uint_as_float(u);
}

__device__ __forceinline__ void mma8(float c[4], const float4& a, float bx, float by) {
    asm("mma.sync.aligned.m16n8k8.row.col.f32.tf32.tf32.f32 "
        "{%0,%1,%2,%3},{%4,%5,%6,%7},{%8,%9},{%0,%1,%2,%3};"
        : "+f"(c[0]), "+f"(c[1]), "+f"(c[2]), "+f"(c[3])
        : "r"(__float_as_uint(a.x)), "r"(__float_as_uint(a.y)),
          "r"(__float_as_uint(a.z)), "r"(__float_as_uint(a.w)),
          "r"(__float_as_uint(bx)), "r"(__float_as_uint(by)));
}

__device__ __forceinline__ void cpa16(uint32_t s, const void* g) {
    asm volatile("cp.async.ca.shared.global [%0], [%1], 16;" :: "r"(s), "l"(g));
}

// ---------------------------------------------------------------------------
// Pre-shuffle Vw [V,H] into B-fragment layout (tf32), one 128-col tile/block.
// ---------------------------------------------------------------------------
__global__ void k_prepB(const float* __restrict__ Vw) {
    extern __shared__ float Bs[];          // 16384 floats (64 KB)
    int nt = blockIdx.x, tid = threadIdx.x;
    int n0 = nt * 128;
    #pragma unroll
    for (int i = 0; i < 16; i++) {
        int f  = tid + i * 256;            // 0..4095 float4 id
        int nn = f >> 5;                   // row in tile
        int c4 = f & 31;                   // float4 within row
        int gn = n0 + nn;
        float4 v = (gn < VV) ? ((const float4*)Vw)[(size_t)gn * 32 + c4]
                             : make_float4(0.f, 0.f, 0.f, 0.f);
        int k0 = c4 * 4;
        int kg = k0 >> 3, ip = nn >> 4;
        int reg  = ((nn >> 3) & 1) * 2 + ((k0 & 7) >> 2);
        int base = (kg * 8 + ip) * 128 + ((nn & 7) << 2) * 4 + reg;
        Bs[base + 0]  = to_tf32(v.x);
        Bs[base + 4]  = to_tf32(v.y);
        Bs[base + 8]  = to_tf32(v.z);
        Bs[base + 12] = to_tf32(v.w);
    }
    __syncthreads();
    float4* dst = (float4*)g_Bfrag + (size_t)nt * 4096;
    #pragma unroll
    for (int i = 0; i < 16; i++)
        dst[tid + i * 256] = ((float4*)Bs)[tid + i * 256];
}

// ---------------------------------------------------------------------------
// ux[m][h] = sum_e x[m][e] * Uw[h][e] + Ub[h] + Wb[h]
// ---------------------------------------------------------------------------
__global__ void k_ux(const float* __restrict__ x, const float* __restrict__ Uw,
                     const float* __restrict__ Ub, const float* __restrict__ Wb) {
    __shared__ float UwT[EE][HH];
    __shared__ float xs[32][EE];
    __shared__ float bias[HH];
    int tid = threadIdx.x;

    for (int f = tid; f < HH * EE / 4; f += 256) {
        int h = f / (EE / 4), c = f % (EE / 4);
        float4 u = ((const float4*)Uw)[f];
        UwT[c * 4 + 0][h] = u.x;
        UwT[c * 4 + 1][h] = u.y;
        UwT[c * 4 + 2][h] = u.z;
        UwT[c * 4 + 3][h] = u.w;
    }
    if (tid < HH) bias[tid] = Ub[tid] + Wb[tid];

    int m0 = blockIdx.x * 32;
    {
        int r = tid / 8, c = tid % 8;
        ((float4*)&xs[r][0])[c] = ((const float4*)x)[(size_t)(m0 + r) * (EE / 4) + c];
    }
    __syncthreads();

    int h = tid % HH;
    int half = tid / HH;
    #pragma unroll
    for (int rr = 0; rr < 16; rr++) {
        int r = half * 16 + rr;
        float acc = bias[h];
        const float4* xv = (const float4*)&xs[r][0];
        #pragma unroll
        for (int e4 = 0; e4 < EE / 4; e4++) {
            float4 xf = xv[e4];
            acc += UwT[e4 * 4 + 0][h] * xf.x;
            acc += UwT[e4 * 4 + 1][h] * xf.y;
            acc += UwT[e4 * 4 + 2][h] * xf.z;
            acc += UwT[e4 * 4 + 3][h] * xf.w;
        }
        g_ux[(size_t)(m0 + r) * HH + h] = acc;
    }
}

// ---------------------------------------------------------------------------
// Recurrence: 256 threads/block, 2 threads per j, Ww register-resident.
// Stores hs directly in A-fragment layout (tf32); final h to out_hidden.
// ---------------------------------------------------------------------------
__global__ void __launch_bounds__(256, 1)
k_rnn(const float* __restrict__ Ww, float* __restrict__ out_hidden) {
    __shared__ float hb[2][HH];
    int tid  = threadIdx.x;
    int j    = tid >> 1;
    int half = tid & 1;
    int b    = blockIdx.x;

    // Each thread owns 64 consecutive Ww[j][k] values (16 float4, coalesced LDG)
    float4 w[16];
    const float4* Ww4 = (const float4*)Ww;
    #pragma unroll
    for (int i = 0; i < 16; i++)
        w[i] = Ww4[(size_t)j * 32 + half * 16 + i];

    if (half == 0) hb[0][j] = 0.0f;
    __syncthreads();

    const float* uxb = g_ux + (size_t)b * TT * HH;

    // Precompute thread-invariant parts of A-frag index (k = j)
    int kg = j >> 3, kl = j & 7;
    int kcol = (kl & 3) * 4 + 2 * (kl >> 2);

    int p = 0;
    float v = 0.0f;
    for (int t = 0; t < TT; t++) {
        const float4* h4 = (const float4*)hb[p] + half * 16;
        float a = 0.f, bb2 = 0.f, c = 0.f, d = 0.f;
        #pragma unroll
        for (int i = 0; i < 16; i++) {
            float4 hv = h4[i];
            a   += w[i].x * hv.x;
            bb2 += w[i].y * hv.y;
            c   += w[i].z * hv.z;
            d   += w[i].w * hv.w;
        }
        float acc = (a + bb2) + (c + d);
        acc += __shfl_xor_sync(0xFFFFFFFFu, acc, 1);
        v = tanhf(acc + uxb[t * HH + j]);
        if (half == 0) {
            hb[1 - p][j] = v;
            int m  = b * TT + t;
            int mt = m >> 6, mr = m & 63;
            int im = mr >> 4, r = mr & 15;
            int idx = mt * 8192 + (kg * 4 + im) * 128
                    + ((r & 7) << 4) + kcol + (r >> 3);
            g_Afrag[idx] = to_tf32(v);
        }
        __syncthreads();
        p ^= 1;
    }
    if (half == 0) out_hidden[b * HH + j] = v;
}

// ---------------------------------------------------------------------------
// Output GEMM: pure-copy loads (cp.async) from pre-shuffled fragments.
// BM=64, BN=128, K=128 resident; 8 warps (2M x 4N), warp does 32x32.
// ---------------------------------------------------------------------------
__global__ void __launch_bounds__(256, 2)
k_gemm(const float* __restrict__ Vb, float* __restrict__ out) {
    extern __shared__ float sm[];
    float* As = sm;                 // 8192 floats (32 KB)
    float* Bs = sm + 8192;          // 16384 floats (64 KB)

    int tid  = threadIdx.x;
    int warp = tid >> 5;
    int lane = tid & 31;
    int mt = blockIdx.y, nt = blockIdx.x;
    int m0 = mt * 64, n0 = nt * 128;

    const float4* Asrc = (const float4*)g_Afrag + (size_t)mt * 2048;
    const float4* Bsrc = (const float4*)g_Bfrag + (size_t)nt * 4096;
    uint32_t sA = (uint32_t)__cvta_generic_to_shared(As);
    uint32_t sB = (uint32_t)__cvta_generic_to_shared(Bs);
    #pragma unroll
    for (int i = 0; i < 8; i++)
        cpa16(sA + (tid + i * 256) * 16, Asrc + tid + i * 256);
    #pragma unroll
    for (int i = 0; i < 16; i++)
        cpa16(sB + (tid + i * 256) * 16, Bsrc + tid + i * 256);
    asm volatile("cp.async.commit_group;");
    asm volatile("cp.async.wait_group 0;");
    __syncthreads();

    int wm = warp >> 2;   // 0..1
    int wn = warp & 3;    // 0..3

    float c[2][4][4];
    #pragma unroll
    for (int a = 0; a < 2; a++)
        #pragma unroll
        for (int b = 0; b < 4; b++)
            #pragma unroll
            for (int d = 0; d < 4; d++) c[a][b][d] = 0.0f;

    const float4* As4 = (const float4*)As;
    const float4* Bs4 = (const float4*)Bs;

    #pragma unroll
    for (int kg = 0; kg < 16; kg++) {
        float4 a0 = As4[(kg * 4 + wm * 2 + 0) * 32 + lane];
        float4 a1 = As4[(kg * 4 + wm * 2 + 1) * 32 + lane];
        float4 b0 = Bs4[(kg * 8 + wn * 2 + 0) * 32 + lane];
        float4 b1 = Bs4[(kg * 8 + wn * 2 + 1) * 32 + lane];
        mma8(c[0][0], a0, b0.x, b0.y);
        mma8(c[0][1], a0, b0.z, b0.w);
        mma8(c[0][2], a0, b1.x, b1.y);
        mma8(c[0][3], a0, b1.z, b1.w);
        mma8(c[1][0], a1, b0.x, b0.y);
        mma8(c[1][1], a1, b0.z, b0.w);
        mma8(c[1][2], a1, b1.x, b1.y);
        mma8(c[1][3], a1, b1.z, b1.w);
    }

    #pragma unroll
    for (int im = 0; im < 2; im++) {
        int row = m0 + wm * 32 + im * 16 + (lane >> 2);
        #pragma unroll
        for (int ntile = 0; ntile < 4; ntile++) {
            int col = n0 + wn * 32 + ntile * 8 + (lane & 3) * 2;
            if (col < VV) {
                float vbx = Vb[col], vby = Vb[col + 1];
                float2 o0 = make_float2(c[im][ntile][0] + vbx, c[im][ntile][1] + vby);
                float2 o1 = make_float2(c[im][ntile][2] + vbx, c[im][ntile][3] + vby);
                *(float2*)(out + (size_t)row * VV + col) = o0;
                *(float2*)(out + (size_t)(row + 8) * VV + col) = o1;
            }
        }
    }
}

// ---------------------------------------------------------------------------
extern "C" void kernel_launch(void* const* d_in, const int* in_sizes, int n_in,
                              void* d_out, int out_size) {
    const float* x  = (const float*)d_in[0];
    const float* Ww = (const float*)d_in[1];
    const float* Wb = (const float*)d_in[2];
    const float* Uw = (const float*)d_in[3];
    const float* Ub = (const float*)d_in[4];
    const float* Vw = (const float*)d_in[5];
    const float* Vb = (const float*)d_in[6];
    float* out = (float*)d_out;

    cudaFuncSetAttribute(k_prepB, cudaFuncAttributeMaxDynamicSharedMemorySize, 65536);
    cudaFuncSetAttribute(k_gemm,  cudaFuncAttributeMaxDynamicSharedMemorySize,
                         (8192 + 16384) * 4);

    k_prepB<<<NT, 256, 65536>>>(Vw);
    k_ux<<<MM / 32, 256>>>(x, Uw, Ub, Wb);
    k_rnn<<<BB, 256>>>(Ww, out + (size_t)MM * VV);
    k_gemm<<<dim3(NT, MT), 256, (8192 + 16384) * 4>>>(Vb, out);
}